// round 6
// baseline (speedup 1.0000x reference)
#include <cuda_runtime.h>
#include <cstdint>

// Skinny GEMM via mma.sync tf32, zero-smem mainloop + fused dual softmax.
// C[65536,40] = embs[65536,1024] @ W^T, W = [W_status(5); W_flight(30); pad]
// Each warp owns 32 tokens; A and B fragments are loaded DIRECTLY from global
// with LDG.128 (K-permutation makes fragment layout coalescible: 8 rows x 64B
// fully-used sectors per instruction). No cp.async, no mainloop syncthreads.
// Raw fp32 bits fed as tf32 (RZ truncate); deterministic bias cancelled by
// corr = 1 + 2*2^-11*ln2 in the epilogue.

#define EMB    1024
#define NS     5
#define NF     30
#define NL     35
#define OUTC   63
#define BM     128
#define LSTR   41
#define NTH    128
#define NKB    (EMB / 16)    // 64 k16 blocks

__device__ __forceinline__ void mma8(float* c, const uint32_t* a, const uint32_t* b) {
    asm volatile(
        "mma.sync.aligned.m16n8k8.row.col.f32.tf32.tf32.f32 "
        "{%0,%1,%2,%3}, {%4,%5,%6,%7}, {%8,%9}, {%0,%1,%2,%3};"
        : "+f"(c[0]), "+f"(c[1]), "+f"(c[2]), "+f"(c[3])
        : "r"(a[0]), "r"(a[1]), "r"(a[2]), "r"(a[3]), "r"(b[0]), "r"(b[1]));
}

__global__ __launch_bounds__(NTH, 4) void aux2_reg_kernel(
    const float* __restrict__ embs,
    const float* __restrict__ W_status,
    const float* __restrict__ b_status,
    const float* __restrict__ W_flight,
    const float* __restrict__ b_flight,
    float* __restrict__ out,
    int ntok)
{
    __shared__ float Ls[BM * LSTR];   // 20,992 B (epilogue only)

    const int tid  = threadIdx.x;
    const int wid  = tid >> 5;
    const int lane = tid & 31;
    const int g    = lane >> 2;     // 0..7
    const int t    = lane & 3;      // 0..3
    const long tokw = (long)blockIdx.x * BM + wid * 32;  // warp's first token

    // A row pointers: rows g, g+8 (m-tile 0) and g+16, g+24 (m-tile 1),
    // starting at this thread's column 4t.
    const uint4* ar[4];
#pragma unroll
    for (int r = 0; r < 4; ++r)
        ar[r] = reinterpret_cast<const uint4*>(
                    embs + (tokw + r * 8 + g) * EMB + 4 * t);

    // B row pointers: row = nt*8 + g (nt = 0..4). Rows >= 35 are padding.
    const uint4* br[5];
    bool bvalid[5];
#pragma unroll
    for (int nt = 0; nt < 5; ++nt) {
        int r = nt * 8 + g;
        bvalid[nt] = (r < NL);
        const float* src = (r < NS) ? (W_status + r * EMB)
                                    : (W_flight + ((r < NL ? r : NS) - NS) * EMB);
        br[nt] = reinterpret_cast<const uint4*>(src + 4 * t);
    }

    float acc[2][5][4];
#pragma unroll
    for (int mt = 0; mt < 2; ++mt)
#pragma unroll
        for (int nt = 0; nt < 5; ++nt)
#pragma unroll
            for (int i = 0; i < 4; ++i) acc[mt][nt][i] = 0.0f;

    // ---- mainloop: 64 k16 blocks; each uint4 = cols [16kb+4t .. +3] ----
#pragma unroll 2
    for (int kb = 0; kb < NKB; ++kb) {
        const int off = kb * 4;     // uint4 index advance: 16 floats per kb

        uint4 a[4];
#pragma unroll
        for (int r = 0; r < 4; ++r) a[r] = ar[r][off];

        uint4 b[5];
#pragma unroll
        for (int nt = 0; nt < 5; ++nt) {
            uint4 v = br[nt][off];
            b[nt] = bvalid[nt] ? v : make_uint4(0u, 0u, 0u, 0u);
        }

        // MMA step 0: k-slots {t, t+4} = cols {4t, 4t+1}
        uint32_t af0[2][4] = {
            { a[0].x, a[1].x, a[0].y, a[1].y },
            { a[2].x, a[3].x, a[2].y, a[3].y } };
        // MMA step 1: cols {4t+2, 4t+3}
        uint32_t af1[2][4] = {
            { a[0].z, a[1].z, a[0].w, a[1].w },
            { a[2].z, a[3].z, a[2].w, a[3].w } };

#pragma unroll
        for (int nt = 0; nt < 5; ++nt) {
            uint32_t bf0[2] = { b[nt].x, b[nt].y };
            uint32_t bf1[2] = { b[nt].z, b[nt].w };
#pragma unroll
            for (int mt = 0; mt < 2; ++mt) {
                mma8(acc[mt][nt], af0[mt], bf0);
                mma8(acc[mt][nt], af1[mt], bf1);
            }
        }
    }

    // ---- epilogue: fragments -> logits smem ----
#pragma unroll
    for (int mt = 0; mt < 2; ++mt)
#pragma unroll
        for (int nt = 0; nt < 5; ++nt) {
            int r0 = wid * 32 + mt * 16 + g;
            int cc = nt * 8 + t * 2;
            if (cc < NL) {
                Ls[r0 * LSTR + cc]       = acc[mt][nt][0];
                Ls[(r0 + 8) * LSTR + cc] = acc[mt][nt][2];
            }
            if (cc + 1 < NL) {
                Ls[r0 * LSTR + cc + 1]       = acc[mt][nt][1];
                Ls[(r0 + 8) * LSTR + cc + 1] = acc[mt][nt][3];
            }
        }
    __syncthreads();

    // ---- per-thread dual softmax + store (thread tid = token) ----
    {
        const float corr = 1.000677f;   // tf32 RZ truncation bias compensation
        float sl[NS], fl[NF];
#pragma unroll
        for (int n = 0; n < NS; ++n) sl[n] = Ls[tid * LSTR + n] * corr + b_status[n];
#pragma unroll
        for (int n = 0; n < NF; ++n) fl[n] = Ls[tid * LSTR + NS + n] * corr + b_flight[n];

        float smax = sl[0];
#pragma unroll
        for (int n = 1; n < NS; ++n) smax = fmaxf(smax, sl[n]);
        float ssum = 0.f;
#pragma unroll
        for (int n = 0; n < NS; ++n) { sl[n] = __expf(sl[n] - smax); ssum += sl[n]; }
        float sinv = 1.f / ssum;
#pragma unroll
        for (int n = 0; n < NS; ++n) sl[n] *= sinv;

        float fm = fl[0];
#pragma unroll
        for (int n = 1; n < NF; ++n) fm = fmaxf(fm, fl[n]);
        float fsum = 0.f;
#pragma unroll
        for (int n = 0; n < NF; ++n) { fl[n] = __expf(fl[n] - fm); fsum += fl[n]; }
        float finv = 1.f / fsum;
#pragma unroll
        for (int n = 0; n < NF; ++n) fl[n] *= finv;

        const float book = sl[4], change = sl[3];
        long token = (long)blockIdx.x * BM + tid;
        if (token < ntok) {
            float* op = out + token * (long)OUTC;
            op[0] = sl[0];
            op[1] = sl[2];
            op[2] = sl[1];
#pragma unroll
            for (int j = 0; j < NF; ++j) {
                op[3 + j]  = book   * fl[j];
                op[33 + j] = change * fl[j];
            }
        }
    }
}

extern "C" void kernel_launch(void* const* d_in, const int* in_sizes, int n_in,
                              void* d_out, int out_size) {
    const float* embs     = (const float*)d_in[0];
    const float* W_status = (const float*)d_in[1];
    const float* b_status = (const float*)d_in[2];
    const float* W_flight = (const float*)d_in[3];
    const float* b_flight = (const float*)d_in[4];
    float* out = (float*)d_out;

    int ntok = in_sizes[0] / EMB;   // 65536
    int blocks = ntok / BM;         // 512
    aux2_reg_kernel<<<blocks, NTH>>>(embs, W_status, b_status,
                                     W_flight, b_flight, out, ntok);
}

// round 8
// speedup vs baseline: 1.0560x; 1.0560x over previous
#include <cuda_runtime.h>
#include <cstdint>

// Skinny GEMM via mma.sync tf32 with per-warp cp.async ring (depth 4).
// C[65536,40] = embs[65536,1024] @ W^T, W = [W_status(5); W_flight(30); pad]
// Warp owns 32 tokens. Each lane cp.asyncs exactly the 4x16B A fragments it
// will itself consume -> no mainloop barriers; wait_group scoreboard decouples
// load issue from MMA consumption (4 stages in flight per warp).
// FIX vs prev round: wait -> LDS-read -> prefetch -> commit ordering, so a
// slot is consumed into registers BEFORE being rewritten (prev version raced).
// B (140KB) read via LDG.128 -> L1/L2-resident hits.
// Raw fp32 bits as tf32 (RZ truncate), bias cancelled by corr in epilogue.

#define EMB    1024
#define NS     5
#define NF     30
#define NL     35
#define OUTC   63
#define BM     128
#define LSTR   41
#define NTH    128
#define NKB    (EMB / 16)    // 64 k16 blocks
#define DEPTH  4

// ring: [warp][stage][r*32+lane] float4 slots = 4*4*128*16B = 32KB
#define STAGE_F4 128
#define WARP_F4  (DEPTH * STAGE_F4)

__device__ __forceinline__ void mma8(float* c, const uint32_t* a, const uint32_t* b) {
    asm volatile(
        "mma.sync.aligned.m16n8k8.row.col.f32.tf32.tf32.f32 "
        "{%0,%1,%2,%3}, {%4,%5,%6,%7}, {%8,%9}, {%0,%1,%2,%3};"
        : "+f"(c[0]), "+f"(c[1]), "+f"(c[2]), "+f"(c[3])
        : "r"(a[0]), "r"(a[1]), "r"(a[2]), "r"(a[3]), "r"(b[0]), "r"(b[1]));
}
__device__ __forceinline__ void cp16s(uint32_t dst, const float* src) {
    asm volatile("cp.async.cg.shared.global [%0], [%1], 16;" :: "r"(dst), "l"(src));
}
__device__ __forceinline__ void cp_commit() { asm volatile("cp.async.commit_group;"); }
template<int N> __device__ __forceinline__ void cp_wait() {
    asm volatile("cp.async.wait_group %0;" :: "n"(N));
}

__global__ __launch_bounds__(NTH, 4) void aux2_ring_kernel(
    const float* __restrict__ embs,
    const float* __restrict__ W_status,
    const float* __restrict__ b_status,
    const float* __restrict__ W_flight,
    const float* __restrict__ b_flight,
    float* __restrict__ out,
    int ntok)
{
    __shared__ __align__(16) char sraw[4 * WARP_F4 * 16];   // 32KB: ring, then Ls alias

    const int tid  = threadIdx.x;
    const int wid  = tid >> 5;
    const int lane = tid & 31;
    const int g    = lane >> 2;     // 0..7
    const int t    = lane & 3;      // 0..3
    const long tokw = (long)blockIdx.x * BM + wid * 32;

    // per-lane global A pointers: row tokw + r*8 + g, col 4t (advance 16 floats/kb)
    const float* gptr[4];
#pragma unroll
    for (int r = 0; r < 4; ++r)
        gptr[r] = embs + (tokw + r * 8 + g) * EMB + 4 * t;

    // per-lane ring slots (shared-space addresses)
    uint32_t ringbase = (uint32_t)__cvta_generic_to_shared(sraw)
                      + (uint32_t)(wid * WARP_F4) * 16u;
    // slot for (stage s, r): ringbase + (s*STAGE_F4 + r*32 + lane)*16

    // B row pointers (rows >= 35 are pad -> masked to zero after load)
    const uint4* br[5];
    bool bvalid[5];
#pragma unroll
    for (int nt = 0; nt < 5; ++nt) {
        int r = nt * 8 + g;
        bvalid[nt] = (r < NL);
        const float* src = (r < NS) ? (W_status + r * EMB)
                                    : (W_flight + ((r < NL ? r : NS) - NS) * EMB);
        br[nt] = reinterpret_cast<const uint4*>(src + 4 * t);
    }

    float acc[2][5][4];
#pragma unroll
    for (int mt = 0; mt < 2; ++mt)
#pragma unroll
        for (int nt = 0; nt < 5; ++nt)
#pragma unroll
            for (int i = 0; i < 4; ++i) acc[mt][nt][i] = 0.0f;

    // ---- prologue: fill stages 0..3, one commit group per stage ----
#pragma unroll
    for (int s = 0; s < DEPTH; ++s) {
#pragma unroll
        for (int r = 0; r < 4; ++r)
            cp16s(ringbase + (uint32_t)(s * STAGE_F4 + r * 32 + lane) * 16u,
                  gptr[r] + s * 16);
        cp_commit();
    }
    // invariant at loop entry: 4 groups pending (stages kb..kb+3)

    // ---- mainloop: wait -> read -> prefetch -> commit; no barriers ----
#pragma unroll 2
    for (int kb = 0; kb < NKB; ++kb) {
        const int s = kb & (DEPTH - 1);

        cp_wait<DEPTH - 1>();   // stage kb's group complete -> slot s readable

        // LDS.128 own fragments into registers (slot s is now consumed)
        uint4 v[4];
#pragma unroll
        for (int r = 0; r < 4; ++r) {
            uint32_t sa = ringbase + (uint32_t)(s * STAGE_F4 + r * 32 + lane) * 16u;
            asm volatile("ld.shared.v4.u32 {%0,%1,%2,%3}, [%4];"
                         : "=r"(v[r].x), "=r"(v[r].y), "=r"(v[r].z), "=r"(v[r].w)
                         : "r"(sa));
        }

        // refill dead slot s with stage kb+DEPTH (LDS above already latched data)
        if (kb + DEPTH < NKB) {
#pragma unroll
            for (int r = 0; r < 4; ++r)
                cp16s(ringbase + (uint32_t)(s * STAGE_F4 + r * 32 + lane) * 16u,
                      gptr[r] + (kb + DEPTH) * 16);
        }
        cp_commit();            // unconditional: keeps group accounting uniform

        uint4 b[5];
#pragma unroll
        for (int nt = 0; nt < 5; ++nt) {
            uint4 w = br[nt][kb * 4];
            b[nt] = bvalid[nt] ? w : make_uint4(0u, 0u, 0u, 0u);
        }

        uint32_t af0[2][4] = {
            { v[0].x, v[1].x, v[0].y, v[1].y },
            { v[2].x, v[3].x, v[2].y, v[3].y } };
        uint32_t af1[2][4] = {
            { v[0].z, v[1].z, v[0].w, v[1].w },
            { v[2].z, v[3].z, v[2].w, v[3].w } };

#pragma unroll
        for (int nt = 0; nt < 5; ++nt) {
            uint32_t bf0[2] = { b[nt].x, b[nt].y };
            uint32_t bf1[2] = { b[nt].z, b[nt].w };
#pragma unroll
            for (int mt = 0; mt < 2; ++mt) {
                mma8(acc[mt][nt], af0[mt], bf0);
                mma8(acc[mt][nt], af1[mt], bf1);
            }
        }
    }

    cp_wait<0>();
    __syncthreads();          // ring dead; alias it as logits buffer

    // ---- epilogue: fragments -> logits smem ----
    float* Ls = reinterpret_cast<float*>(sraw);   // 128*41*4 = 21KB < 32KB
#pragma unroll
    for (int mt = 0; mt < 2; ++mt)
#pragma unroll
        for (int nt = 0; nt < 5; ++nt) {
            int r0 = wid * 32 + mt * 16 + g;
            int cc = nt * 8 + t * 2;
            if (cc < NL) {
                Ls[r0 * LSTR + cc]       = acc[mt][nt][0];
                Ls[(r0 + 8) * LSTR + cc] = acc[mt][nt][2];
            }
            if (cc + 1 < NL) {
                Ls[r0 * LSTR + cc + 1]       = acc[mt][nt][1];
                Ls[(r0 + 8) * LSTR + cc + 1] = acc[mt][nt][3];
            }
        }
    __syncthreads();

    // ---- per-thread dual softmax + store ----
    {
        const float corr = 1.000677f;   // tf32 RZ truncation bias compensation
        float sl[NS], fl[NF];
#pragma unroll
        for (int n = 0; n < NS; ++n) sl[n] = Ls[tid * LSTR + n] * corr + b_status[n];
#pragma unroll
        for (int n = 0; n < NF; ++n) fl[n] = Ls[tid * LSTR + NS + n] * corr + b_flight[n];

        float smax = sl[0];
#pragma unroll
        for (int n = 1; n < NS; ++n) smax = fmaxf(smax, sl[n]);
        float ssum = 0.f;
#pragma unroll
        for (int n = 0; n < NS; ++n) { sl[n] = __expf(sl[n] - smax); ssum += sl[n]; }
        float sinv = 1.f / ssum;
#pragma unroll
        for (int n = 0; n < NS; ++n) sl[n] *= sinv;

        float fm = fl[0];
#pragma unroll
        for (int n = 1; n < NF; ++n) fm = fmaxf(fm, fl[n]);
        float fsum = 0.f;
#pragma unroll
        for (int n = 0; n < NF; ++n) { fl[n] = __expf(fl[n] - fm); fsum += fl[n]; }
        float finv = 1.f / fsum;
#pragma unroll
        for (int n = 0; n < NF; ++n) fl[n] *= finv;

        const float book = sl[4], change = sl[3];
        long token = (long)blockIdx.x * BM + tid;
        if (token < ntok) {
            float* op = out + token * (long)OUTC;
            op[0] = sl[0];
            op[1] = sl[2];
            op[2] = sl[1];
#pragma unroll
            for (int j = 0; j < NF; ++j) {
                op[3 + j]  = book   * fl[j];
                op[33 + j] = change * fl[j];
            }
        }
    }
}

extern "C" void kernel_launch(void* const* d_in, const int* in_sizes, int n_in,
                              void* d_out, int out_size) {
    const float* embs     = (const float*)d_in[0];
    const float* W_status = (const float*)d_in[1];
    const float* b_status = (const float*)d_in[2];
    const float* W_flight = (const float*)d_in[3];
    const float* b_flight = (const float*)d_in[4];
    float* out = (float*)d_out;

    int ntok = in_sizes[0] / EMB;   // 65536
    int blocks = ntok / BM;         // 512
    aux2_ring_kernel<<<blocks, NTH>>>(embs, W_status, b_status,
                                      W_flight, b_flight, out, ntok);
}